// round 12
// baseline (speedup 1.0000x reference)
#include <cuda_runtime.h>
#include <cuda_bf16.h>
#include <cuda_fp16.h>
#include <math.h>

#define SEQL   2048
#define BATCH  64
#define INDIM  512
#define HID    512
#define NCTA   128
#define NTHR   512
#define APITCH 520                    // bf16/fp16 elems per padded row (1040 B)

// ---------------- global scratch ----------------
__device__ unsigned g_flags[NCTA];                                   // monotonic across runs
__device__ __align__(16) __nv_bfloat16 g_xs[(size_t)SEQL * 2 * BATCH * APITCH];
__device__ __align__(16) float g_P[(size_t)SEQL * NCTA * 1024];      // [t][cta][64b][16r]
__device__ __align__(16) __half g_hf[2][BATCH * APITCH];             // ping-pong fp16 h

__device__ __forceinline__ float sigm(float x){ return 1.0f/(1.0f+__expf(-x)); }

// ---- cp.async ----
__device__ __forceinline__ void cp16(unsigned s, const void* g){
    asm volatile("cp.async.cg.shared.global [%0], [%1], 16;" :: "r"(s), "l"(g) : "memory");
}
__device__ __forceinline__ void cp_commit(){ asm volatile("cp.async.commit_group;" ::: "memory"); }
template<int N> __device__ __forceinline__ void cp_wait(){
    asm volatile("cp.async.wait_group %0;" :: "n"(N) : "memory");
}

// ---- release/acquire flags ----
__device__ __forceinline__ void st_rel(unsigned* p, unsigned v){
    asm volatile("st.release.gpu.u32 [%0], %1;" :: "l"(p), "r"(v) : "memory");
}
__device__ __forceinline__ unsigned ld_acq(unsigned* p){
    unsigned v; asm volatile("ld.acquire.gpu.u32 %0, [%1];" : "=r"(v) : "l"(p) : "memory");
    return v;
}

// ---- tensor-core primitives ----
__device__ __forceinline__ void ldsm4(unsigned a, unsigned &r0, unsigned &r1,
                                      unsigned &r2, unsigned &r3){
    asm volatile("ldmatrix.sync.aligned.m8n8.x4.shared.b16 {%0,%1,%2,%3}, [%4];"
                 : "=r"(r0), "=r"(r1), "=r"(r2), "=r"(r3) : "r"(a));
}
__device__ __forceinline__ void ldsm2(unsigned a, unsigned &r0, unsigned &r1){
    asm volatile("ldmatrix.sync.aligned.m8n8.x2.shared.b16 {%0,%1}, [%2];"
                 : "=r"(r0), "=r"(r1) : "r"(a));
}
__device__ __forceinline__ void mmabf(float &c0, float &c1, float &c2, float &c3,
                                      unsigned a0, unsigned a1, unsigned a2, unsigned a3,
                                      unsigned b0, unsigned b1){
    asm volatile("mma.sync.aligned.m16n8k16.row.col.f32.bf16.bf16.f32 "
                 "{%0,%1,%2,%3}, {%4,%5,%6,%7}, {%8,%9}, {%0,%1,%2,%3};"
                 : "+f"(c0), "+f"(c1), "+f"(c2), "+f"(c3)
                 : "r"(a0), "r"(a1), "r"(a2), "r"(a3), "r"(b0), "r"(b1));
}
__device__ __forceinline__ void mmaf16(float &c0, float &c1, float &c2, float &c3,
                                       unsigned a0, unsigned a1, unsigned a2, unsigned a3,
                                       unsigned b0, unsigned b1){
    asm volatile("mma.sync.aligned.m16n8k16.row.col.f32.f16.f16.f32 "
                 "{%0,%1,%2,%3}, {%4,%5,%6,%7}, {%8,%9}, {%0,%1,%2,%3};"
                 : "+f"(c0), "+f"(c1), "+f"(c2), "+f"(c3)
                 : "r"(a0), "r"(a1), "r"(a2), "r"(a3), "r"(b0), "r"(b1));
}

// ============ kernel 1: x fp32 -> bf16 hi/lo split ============
__global__ void __launch_bounds__(256, 4)
xconv(const float* __restrict__ in)
{
    int t = blockIdx.x;
    const float2* src = (const float2*)(in + (size_t)t * BATCH * INDIM);
    __nv_bfloat16* dhi = g_xs + (size_t)t * 2 * BATCH * APITCH;
    __nv_bfloat16* dlo = dhi + BATCH * APITCH;
    for (int i = threadIdx.x; i < BATCH * INDIM / 2; i += 256) {
        int b = i >> 8, kk = i & 255;
        float2 v = src[(size_t)b * 256 + kk];
        __nv_bfloat16 h0 = __float2bfloat16(v.x);
        __nv_bfloat16 h1 = __float2bfloat16(v.y);
        __nv_bfloat162 hp; hp.x = h0; hp.y = h1;
        __nv_bfloat162 lp;
        lp.x = __float2bfloat16(v.x - __bfloat162float(h0));
        lp.y = __float2bfloat16(v.y - __bfloat162float(h1));
        ((__nv_bfloat162*)(dhi + b * APITCH))[kk] = hp;
        ((__nv_bfloat162*)(dlo + b * APITCH))[kk] = lp;
    }
}

// ============ kernel 2: xproj GEMM  P = x @ Wih^T + (bih + bhh) ============
// grid 128 = 64 row-groups (32 gate rows = 2 rec-CTAs) x 2 t-chunks (1024 t)
#define XP_XBUF 67584u                 // 2 comps * 64 rows * 528 B
#define XP_W    135168                 // weight region offset
#define XP_SMEM 201728                 // + 2 comps * 32 rows * 1040 B

__global__ void __launch_bounds__(NTHR, 1)
xproj(const float* __restrict__ Wih,
      const float* __restrict__ bih,
      const float* __restrict__ bhh)
{
    extern __shared__ char sm[];
    const unsigned sb = (unsigned)__cvta_generic_to_shared(sm);
    const unsigned sx = sb;
    const int tid = threadIdx.x;
    const int rg  = blockIdx.x >> 1;
    const int t0  = (blockIdx.x & 1) * 1024;

    // resident Wih slice (32 rows), bf16 hi/lo
    for (int i = tid; i < 32 * 512; i += NTHR) {
        int rl = i >> 9, k = i & 511;
        int g = (rl & 15) >> 2, hcl = rl & 3, rcta = 2 * rg + (rl >> 4);
        int grow = g * 512 + rcta * 4 + hcl;
        float w = Wih[(size_t)grow * INDIM + k];
        __nv_bfloat16 h = __float2bfloat16(w);
        *(__nv_bfloat16*)(sm + XP_W + rl * 1040 + k * 2) = h;
        *(__nv_bfloat16*)(sm + XP_W + 33280 + rl * 1040 + k * 2) =
            __float2bfloat16(w - __bfloat162float(h));
    }

    const int wid = tid >> 5, lane = tid & 31;
    const int mt = wid & 3, nt = wid >> 2;           // nt 0..3 over 32 rows
    const int n0 = nt * 8 + (lane & 3) * 2;
    const int b  = mt * 16 + (lane >> 2);
    const int rcta0 = 2 * rg + (n0 >> 4);
    const int r0 = n0 & 15;

    int g0 = (n0 & 15) >> 2, h0c = n0 & 3;
    int grow0 = g0 * 512 + rcta0 * 4 + h0c;          // grow(n0+1) = grow0+1
    float bias0 = bih[grow0] + bhh[grow0];
    float bias1 = bih[grow0 + 1] + bhh[grow0 + 1];

    const unsigned aHiBase = sx + (unsigned)((mt * 16 + (lane & 15)) * 528 + (lane >> 4) * 16);
    const unsigned bBase   = sb + XP_W + (unsigned)((nt * 8 + (lane & 7)) * 1040
                                                    + ((lane >> 3) & 1) * 16);

    auto stage = [&](int tt, int hf, int buf){
        const __nv_bfloat16* base = g_xs + (size_t)tt * 2 * BATCH * APITCH;
#pragma unroll
        for (int j = 0; j < 8; ++j) {
            int i = tid + j * NTHR;
            int comp = i >> 11, row = (i >> 5) & 63, u = i & 31;
            cp16(sx + (unsigned)buf * XP_XBUF + (unsigned)(comp * 33792 + row * 528 + u * 16),
                 base + (size_t)comp * BATCH * APITCH + row * APITCH + hf * 256 + u * 8);
        }
        cp_commit();
    };

    __syncthreads();                                  // weights visible
    stage(t0, 0, 0);
    stage(t0, 1, 1);

    float c0 = bias0, c1 = bias1, c2 = bias0, c3 = bias1;

    for (int it = 0; it < 2048; ++it) {
        int hf = it & 1, buf = it & 1;
        int tt = t0 + (it >> 1);
        cp_wait<1>(); __syncthreads();
        unsigned aH = aHiBase + (unsigned)buf * XP_XBUF;
        unsigned aL = aH + 33792u;
        unsigned bB = bBase + (unsigned)(hf * 512);
#pragma unroll 4
        for (int c = 0; c < 16; ++c) {
            unsigned ah0,ah1,ah2,ah3, al0,al1,al2,al3, bh0,bh1, bl0,bl1;
            ldsm4(aH + c * 32, ah0,ah1,ah2,ah3);
            ldsm4(aL + c * 32, al0,al1,al2,al3);
            ldsm2(bB + c * 32, bh0,bh1);
            ldsm2(bB + 33280 + c * 32, bl0,bl1);
            mmabf(c0,c1,c2,c3, ah0,ah1,ah2,ah3, bh0,bh1);
            mmabf(c0,c1,c2,c3, al0,al1,al2,al3, bh0,bh1);
            mmabf(c0,c1,c2,c3, ah0,ah1,ah2,ah3, bl0,bl1);
        }
        if (hf) {
            float* base = g_P + ((size_t)tt * NCTA + rcta0) * 1024;
            *(float2*)(base + b * 16 + r0)       = make_float2(c0, c1);
            *(float2*)(base + (b + 8) * 16 + r0) = make_float2(c2, c3);
            c0 = bias0; c1 = bias1; c2 = bias0; c3 = bias1;
        }
        __syncthreads();
        if (it + 2 < 2048) stage(t0 + ((it + 2) >> 1), (it + 2) & 1, buf);
    }
}

// ============ kernel 3: persistent recurrence (fp16 h) ============
#define R_H    0
#define R_W    66560                   // 16 rows * 1040 B * 2 comps
#define R_PART 99840                   // float [2][64][18]
#define R_PS   109056                  // float [2][64][20]
#define R_F0   119296
#define R_SMEM 119312

__global__ void __launch_bounds__(NTHR, 1)
lstm_rec(const float* __restrict__ Whh, float* __restrict__ out)
{
    extern __shared__ char sm[];
    const unsigned sb = (unsigned)__cvta_generic_to_shared(sm);
    float* part = (float*)(sm + R_PART);
    float* ps   = (float*)(sm + R_PS);
    unsigned* sF0 = (unsigned*)(sm + R_F0);

    const int tid = threadIdx.x;
    const int cta = blockIdx.x;
    const int hc0 = cta * 4;

    if (tid == 0) *sF0 = g_flags[cta];

    // resident Whh slice (16 rows), fp16 hi/lo
    for (int i = tid; i < 16 * 512; i += NTHR) {
        int r = i >> 9, k = i & 511;
        int grow = (r >> 2) * 512 + hc0 + (r & 3);
        float w = Whh[(size_t)grow * HID + k];
        __half h = __float2half(w);
        *(__half*)(sm + R_W + r * 1040 + k * 2) = h;
        *(__half*)(sm + R_W + 16640 + r * 1040 + k * 2) =
            __float2half(w - __half2float(h));
    }

    // warp identity: mt(4 batch) x nt(2 row-tiles) x kh(2 K-halves)
    const int wid = tid >> 5, lane = tid & 31;
    const int mt = wid & 3, nt = (wid >> 2) & 1, kh = wid >> 3;

    const unsigned aHBase = sb + (unsigned)(R_H + (mt * 16 + (lane & 15)) * 1040
                                            + (lane >> 4) * 16 + kh * 512);
    const unsigned bHoist = sb + (unsigned)(R_W + (nt * 8 + (lane & 7)) * 1040
                                            + ((lane >> 3) & 1) * 16 + kh * 512);

    const int prow = mt * 16 + (lane >> 2);
    const int pcol = nt * 8 + (lane & 3) * 2;
    float* pp = part + (kh * 64 + prow) * 18 + pcol;

    const int ub = tid >> 2, uhcl = tid & 3;

    // ps(0) prefetch (warps 8-15)
    if (tid >= 256) {
        int i = tid - 256, bb = i >> 2, r4 = i & 3;
        cp16(sb + (unsigned)(R_PS + bb * 80 + r4 * 16),
             g_P + (size_t)cta * 1024 + bb * 16 + r4 * 4);
        cp_commit();
    }

    __syncthreads();                                  // weights + sF0 visible
    const unsigned F0 = *sF0;

    // hoist Whh b-fragments (hi + lo) for this warp's K-half
    unsigned bh0[16], bh1[16], bl0[16], bl1[16];
#pragma unroll
    for (int c = 0; c < 16; ++c) {
        ldsm2(bHoist + c * 32,         bh0[c], bh1[c]);
        ldsm2(bHoist + 16640 + c * 32, bl0[c], bl1[c]);
    }

    float cst = 0.0f;

    for (int t = 0; t < SEQL; ++t) {
        float c0 = 0.f, c1 = 0.f, c2 = 0.f, c3 = 0.f;

        if (t > 0) {
            // distributed poll: warp w checks 8 flags
            {
                unsigned tgt = F0 + (unsigned)t;
                unsigned* fp = &g_flags[(wid << 3) + (lane & 7)];
                for (;;) {
                    unsigned f = ld_acq(fp);
                    if (__all_sync(0xffffffffu, (int)(f - tgt) >= 0)) break;
                }
            }
            __syncthreads();                          // h buffer fully dead

            const __half* hsrc = g_hf[(t - 1) & 1];
            if (tid < 256) {
                // kh0 group stages + consumes K-half A (cols 0..255)
#pragma unroll
                for (int j = 0; j < 8; ++j) {
                    int i = tid + j * 256, row = i >> 5, u = i & 31;
                    cp16(sb + (unsigned)(R_H + row * 1040 + u * 16),
                         hsrc + row * APITCH + u * 8);
                }
                cp_commit(); cp_wait<0>();
                asm volatile("bar.sync 2, 256;" ::: "memory");
            } else {
                // kh1 group stages + consumes K-half B (cols 256..511)
#pragma unroll
                for (int j = 0; j < 8; ++j) {
                    int i = (tid - 256) + j * 256, row = i >> 5, u = i & 31;
                    cp16(sb + (unsigned)(R_H + row * 1040 + (32 + u) * 16),
                         hsrc + row * APITCH + 256 + u * 8);
                }
                cp_commit(); cp_wait<0>();            // also drains ps(t) group
                asm volatile("bar.sync 3, 256;" ::: "memory");
            }

            // h-MMA: 16 chunks x 2 products (b from regs)
#pragma unroll 4
            for (int c = 0; c < 16; ++c) {
                unsigned a0, a1, a2, a3;
                ldsm4(aHBase + c * 32, a0, a1, a2, a3);
                mmaf16(c0,c1,c2,c3, a0,a1,a2,a3, bh0[c], bh1[c]);
                mmaf16(c0,c1,c2,c3, a0,a1,a2,a3, bl0[c], bl1[c]);
            }
        } else {
            if (tid >= 256) cp_wait<0>();             // ps(0) landed
        }

        // K-half partials
        *(float2*)pp         = make_float2(c0, c1);
        *(float2*)(pp + 144) = make_float2(c2, c3);
        __syncthreads();                              // partials + ps(t) visible

        if (tid < 256) {
            const float* psb = ps + (t & 1) * 1280;
            float sv[4];
#pragma unroll
            for (int g = 0; g < 4; ++g) {
                int r = g * 4 + uhcl;
                // NOTE: bias lives inside ps (added in xproj) — do NOT add it again
                sv[g] = part[ub * 18 + r] + part[(64 + ub) * 18 + r] + psb[ub * 20 + r];
            }
            float ig = sigm(sv[0]);
            float fg = sigm(sv[1]);
            float gv = tanhf(sv[2]);
            float og = sigm(sv[3]);
            float cn = fmaf(fg, cst, ig * gv);
            cst = cn;
            float hn = og * tanhf(cn);

            out[(size_t)t * BATCH * HID + (size_t)ub * HID + hc0 + uhcl] = hn;
            if (t == SEQL - 1)
                out[(size_t)SEQL * BATCH * HID + (size_t)ub * HID + hc0 + uhcl] = hn;

            g_hf[t & 1][ub * APITCH + hc0 + uhcl] = __float2half(hn);

            asm volatile("bar.sync 1, 256;" ::: "memory");
            if (tid == 0) st_rel(&g_flags[cta], F0 + (unsigned)(t + 1));
        } else {
            if (t + 1 < SEQL) {
                int i = tid - 256, bb = i >> 2, r4 = i & 3;
                cp16(sb + (unsigned)(R_PS + ((t + 1) & 1) * 5120 + bb * 80 + r4 * 16),
                     g_P + ((size_t)(t + 1) * NCTA + cta) * 1024 + bb * 16 + r4 * 4);
                cp_commit();
            }
        }
    }

    // c_n
    if (tid < 256)
        out[(size_t)SEQL * BATCH * HID + (size_t)BATCH * HID
            + (size_t)ub * HID + hc0 + uhcl] = cst;
}

extern "C" void kernel_launch(void* const* d_in, const int* in_sizes, int n_in,
                              void* d_out, int out_size)
{
    const float* input = (const float*)d_in[0];
    const float* Wih   = (const float*)d_in[1];
    const float* Whh   = (const float*)d_in[2];
    const float* bih   = (const float*)d_in[3];
    const float* bhh   = (const float*)d_in[4];
    float* out = (float*)d_out;

    static int configured = 0;
    if (!configured) {
        cudaFuncSetAttribute(xproj,
                             cudaFuncAttributeMaxDynamicSharedMemorySize, XP_SMEM);
        cudaFuncSetAttribute(lstm_rec,
                             cudaFuncAttributeMaxDynamicSharedMemorySize, R_SMEM);
        configured = 1;
    }

    xconv<<<SEQL, 256>>>(input);
    xproj<<<NCTA, NTHR, XP_SMEM>>>(Wih, bih, bhh);
    lstm_rec<<<NCTA, NTHR, R_SMEM>>>(Whh, out);
}

// round 13
// speedup vs baseline: 2.0193x; 2.0193x over previous
#include <cuda_runtime.h>
#include <cuda_fp16.h>
#include <math.h>

#define SEQL   2048
#define BATCH  64
#define INDIM  512
#define HID    512
#define NCTA   128
#define NTHR   512

// smem byte offsets
#define ACT_OFF   0               // 64 rows x 1040 B (fp16 activations, 512 cols used)
#define WIH_HI    66560           // 16 rows x 1040 B
#define WIH_LO    83200
#define WHH_HI    99840
#define WHH_LO    116480
#define P_OFF     133120          // float [2][64][18]
#define BIAS_OFF  142336          // 16 floats
#define F0_OFF    142400
#define SMEM_TOTAL 142416

__device__ unsigned g_flags[NCTA];                               // monotonic across runs
__device__ __align__(16) __half g_xh[(size_t)SEQL * BATCH * 512]; // fp16 x
__device__ __align__(16) __half g_hf[2][BATCH * 512];             // ping-pong fp16 h

__device__ __forceinline__ float sigm(float x){ return 1.0f/(1.0f+__expf(-x)); }

// ---- cp.async ----
__device__ __forceinline__ void cp16(unsigned s, const void* g){
    asm volatile("cp.async.cg.shared.global [%0], [%1], 16;" :: "r"(s), "l"(g) : "memory");
}
__device__ __forceinline__ void cp_commit(){ asm volatile("cp.async.commit_group;" ::: "memory"); }
template<int N> __device__ __forceinline__ void cp_wait(){
    asm volatile("cp.async.wait_group %0;" :: "n"(N) : "memory");
}

// ---- release/acquire flags ----
__device__ __forceinline__ void st_rel(unsigned* p, unsigned v){
    asm volatile("st.release.gpu.u32 [%0], %1;" :: "l"(p), "r"(v) : "memory");
}
__device__ __forceinline__ unsigned ld_acq(unsigned* p){
    unsigned v; asm volatile("ld.acquire.gpu.u32 %0, [%1];" : "=r"(v) : "l"(p) : "memory");
    return v;
}

// ---- tensor-core primitives ----
__device__ __forceinline__ void ldsm4(unsigned a, unsigned &r0, unsigned &r1,
                                      unsigned &r2, unsigned &r3){
    asm volatile("ldmatrix.sync.aligned.m8n8.x4.shared.b16 {%0,%1,%2,%3}, [%4];"
                 : "=r"(r0), "=r"(r1), "=r"(r2), "=r"(r3) : "r"(a));
}
__device__ __forceinline__ void ldsm2(unsigned a, unsigned &r0, unsigned &r1){
    asm volatile("ldmatrix.sync.aligned.m8n8.x2.shared.b16 {%0,%1}, [%2];"
                 : "=r"(r0), "=r"(r1) : "r"(a));
}
__device__ __forceinline__ void mmaf16(float &c0, float &c1, float &c2, float &c3,
                                       unsigned a0, unsigned a1, unsigned a2, unsigned a3,
                                       unsigned b0, unsigned b1){
    asm volatile("mma.sync.aligned.m16n8k16.row.col.f32.f16.f16.f32 "
                 "{%0,%1,%2,%3}, {%4,%5,%6,%7}, {%8,%9}, {%0,%1,%2,%3};"
                 : "+f"(c0), "+f"(c1), "+f"(c2), "+f"(c3)
                 : "r"(a0), "r"(a1), "r"(a2), "r"(a3), "r"(b0), "r"(b1));
}

// ============ kernel 1: x fp32 -> fp16 ============
__global__ void __launch_bounds__(256, 4)
xconv(const float* __restrict__ in)
{
    int t = blockIdx.x;
    const float4* src = (const float4*)(in + (size_t)t * BATCH * INDIM);
    __half2* dst = (__half2*)(g_xh + (size_t)t * BATCH * 512);
    for (int i = threadIdx.x; i < BATCH * INDIM / 4; i += 256) {
        float4 v = src[i];
        dst[i * 2]     = __floats2half2_rn(v.x, v.y);
        dst[i * 2 + 1] = __floats2half2_rn(v.z, v.w);
    }
}

// ============ kernel 2: fused persistent LSTM ============
__global__ void __launch_bounds__(NTHR, 1)
lstm_persistent(const float* __restrict__ Wih,
                const float* __restrict__ Whh,
                const float* __restrict__ bih,
                const float* __restrict__ bhh,
                float* __restrict__ out)
{
    extern __shared__ char sm[];
    const unsigned sb = (unsigned)__cvta_generic_to_shared(sm);
    float* part = (float*)(sm + P_OFF);
    float* bias = (float*)(sm + BIAS_OFF);
    unsigned* sF0 = (unsigned*)(sm + F0_OFF);

    const int tid = threadIdx.x;
    const int cta = blockIdx.x;
    const int hc0 = cta * 4;

    if (tid == 0) *sF0 = g_flags[cta];

    // ---- resident weights (16 gate rows), fp16 hi/lo ----
    for (int i = tid; i < 16 * 512; i += NTHR) {
        int r = i >> 9, k = i & 511;
        int grow = (r >> 2) * 512 + hc0 + (r & 3);
        float w = Wih[(size_t)grow * INDIM + k];
        __half h = __float2half(w);
        *(__half*)(sm + WIH_HI + r * 1040 + k * 2) = h;
        *(__half*)(sm + WIH_LO + r * 1040 + k * 2) = __float2half(w - __half2float(h));
        w = Whh[(size_t)grow * HID + k];
        h = __float2half(w);
        *(__half*)(sm + WHH_HI + r * 1040 + k * 2) = h;
        *(__half*)(sm + WHH_LO + r * 1040 + k * 2) = __float2half(w - __half2float(h));
    }
    if (tid < 16) {
        int grow = (tid >> 2) * 512 + hc0 + (tid & 3);
        bias[tid] = bih[grow] + bhh[grow];
    }

    // ---- warp identity: mt(4 batch-tiles) x nt(2 row-tiles) x kh(2 K-halves) ----
    const int wid = tid >> 5, lane = tid & 31;
    const int mt = wid & 3, nt = (wid >> 2) & 1, kh = wid >> 3;

    const unsigned aBase = sb + (unsigned)(ACT_OFF + (mt * 16 + (lane & 15)) * 1040
                                           + (lane >> 4) * 16 + kh * 512);
    const unsigned bIhHi = sb + (unsigned)(WIH_HI + (nt * 8 + (lane & 7)) * 1040
                                           + ((lane >> 3) & 1) * 16 + kh * 512);
    const unsigned bIhLo = bIhHi + (WIH_LO - WIH_HI);
    const unsigned bHhHi = sb + (unsigned)(WHH_HI + (nt * 8 + (lane & 7)) * 1040
                                           + ((lane >> 3) & 1) * 16 + kh * 512);
    const unsigned bHhLo = bHhHi + (WHH_LO - WHH_HI);

    const int prow = mt * 16 + (lane >> 2);
    const int pcol = nt * 8 + (lane & 3) * 2;
    float* pp = part + (kh * 64 + prow) * 18 + pcol;

    const int ub = tid >> 2, uhcl = tid & 3;

    float cst = 0.0f;

    // ---- prefetch x_0 (all 512 threads) ----
    {
        const __half* gx = g_xh;
        for (int i = tid; i < 4096; i += NTHR) {
            int row = i >> 6, u = i & 63;
            cp16(sb + (unsigned)(ACT_OFF + row * 1040 + u * 16), gx + row * 512 + u * 8);
        }
        cp_commit();
    }
    __syncthreads();
    const unsigned F0 = *sF0;

    // ---- hoist Whh b-fragments (hi + lo) for this warp's K-half ----
    unsigned wh0[16], wh1[16], wl0[16], wl1[16];
#pragma unroll
    for (int c = 0; c < 16; ++c) {
        ldsm2(bHhHi + c * 32, wh0[c], wh1[c]);
        ldsm2(bHhLo + c * 32, wl0[c], wl1[c]);
    }

    for (int t = 0; t < SEQL; ++t) {
        cp_wait<0>(); __syncthreads();               // x_t staged

        float c0 = 0.f, c1 = 0.f, c2 = 0.f, c3 = 0.f;
        unsigned a0,a1,a2,a3, b0,b1, d0,d1;

        // ---- x-GEMM chunks 0..7 (region A of x consumed after this) ----
#pragma unroll 4
        for (int c = 0; c < 8; ++c) {
            unsigned off = c * 32;
            ldsm4(aBase + off, a0,a1,a2,a3);
            ldsm2(bIhHi + off, b0,b1);
            ldsm2(bIhLo + off, d0,d1);
            mmaf16(c0,c1,c2,c3, a0,a1,a2,a3, b0,b1);
            mmaf16(c0,c1,c2,c3, a0,a1,a2,a3, d0,d1);
        }

        if (t > 0) {
            // ---- distributed poll: warp w checks flags[w*8 .. w*8+7] ----
            {
                unsigned tgt = F0 + (unsigned)t;
                unsigned* fp = &g_flags[(wid << 3) + (lane & 7)];
                for (;;) {
                    unsigned f = ld_acq(fp);
                    if (__all_sync(0xffffffffu, (int)(f - tgt) >= 0)) break;
                }
            }
            __syncthreads();                          // flags seen; x region A dead

            const __half* hsrc = g_hf[(t - 1) & 1];
            // ---- stage h region A: cols [0,128)∪[256,384) ----
#pragma unroll
            for (int j = 0; j < 4; ++j) {
                int i = tid + j * NTHR;               // 0..2047
                int row = i >> 5, v = i & 31;
                int u = (v < 16) ? v : (v + 16);
                cp16(sb + (unsigned)(ACT_OFF + row * 1040 + u * 16), hsrc + row * 512 + u * 8);
            }
            cp_commit();

            // ---- x-GEMM chunks 8..15 (covers region-A flight) ----
#pragma unroll 4
            for (int c = 8; c < 16; ++c) {
                unsigned off = c * 32;
                ldsm4(aBase + off, a0,a1,a2,a3);
                ldsm2(bIhHi + off, b0,b1);
                ldsm2(bIhLo + off, d0,d1);
                mmaf16(c0,c1,c2,c3, a0,a1,a2,a3, b0,b1);
                mmaf16(c0,c1,c2,c3, a0,a1,a2,a3, d0,d1);
            }
            __syncthreads();                          // x region B dead

            // ---- stage h region B: cols [128,256)∪[384,512) ----
#pragma unroll
            for (int j = 0; j < 4; ++j) {
                int i = tid + j * NTHR;
                int row = i >> 5, v = i & 31;
                int u = (v < 16) ? (v + 16) : (v + 32);
                cp16(sb + (unsigned)(ACT_OFF + row * 1040 + u * 16), hsrc + row * 512 + u * 8);
            }
            cp_commit();

            cp_wait<1>(); __syncthreads();            // h region A landed
#pragma unroll 4
            for (int c = 0; c < 8; ++c) {             // h-MMA region A (b from regs)
                ldsm4(aBase + c * 32, a0,a1,a2,a3);
                mmaf16(c0,c1,c2,c3, a0,a1,a2,a3, wh0[c], wh1[c]);
                mmaf16(c0,c1,c2,c3, a0,a1,a2,a3, wl0[c], wl1[c]);
            }
            cp_wait<0>(); __syncthreads();            // h region B landed
#pragma unroll 4
            for (int c = 8; c < 16; ++c) {            // h-MMA region B
                ldsm4(aBase + c * 32, a0,a1,a2,a3);
                mmaf16(c0,c1,c2,c3, a0,a1,a2,a3, wh0[c], wh1[c]);
                mmaf16(c0,c1,c2,c3, a0,a1,a2,a3, wl0[c], wl1[c]);
            }
        } else {
            // t == 0: finish x-GEMM only
#pragma unroll 4
            for (int c = 8; c < 16; ++c) {
                unsigned off = c * 32;
                ldsm4(aBase + off, a0,a1,a2,a3);
                ldsm2(bIhHi + off, b0,b1);
                ldsm2(bIhLo + off, d0,d1);
                mmaf16(c0,c1,c2,c3, a0,a1,a2,a3, b0,b1);
                mmaf16(c0,c1,c2,c3, a0,a1,a2,a3, d0,d1);
            }
        }

        // ---- K-half partials ----
        pp[0] = c0; pp[1] = c1; pp[144] = c2; pp[145] = c3;
        __syncthreads();                              // partials ready; act buffer dead

        if (tid < 256) {
            // gate update: one (b, hcl) per thread
            float sv[4];
#pragma unroll
            for (int g = 0; g < 4; ++g) {
                int r = g * 4 + uhcl;
                sv[g] = bias[r] + part[ub * 18 + r] + part[(64 + ub) * 18 + r];
            }
            float ig = sigm(sv[0]);
            float fg = sigm(sv[1]);
            float gv = tanhf(sv[2]);
            float og = sigm(sv[3]);
            float cn = fmaf(fg, cst, ig * gv);
            cst = cn;
            float hn = og * tanhf(cn);

            out[(size_t)t * BATCH * HID + (size_t)ub * HID + hc0 + uhcl] = hn;
            if (t == SEQL - 1)
                out[(size_t)SEQL * BATCH * HID + (size_t)ub * HID + hc0 + uhcl] = hn;

            g_hf[t & 1][ub * 512 + hc0 + uhcl] = __float2half(hn);

            asm volatile("bar.sync 1, 256;" ::: "memory");   // h stores done
            if (tid == 0) st_rel(&g_flags[cta], F0 + (unsigned)(t + 1));
        } else {
            // warps 8-15: prefetch x_{t+1} during update/release
            if (t + 1 < SEQL) {
                const __half* gx = g_xh + (size_t)(t + 1) * BATCH * 512;
                for (int i = tid - 256; i < 4096; i += 256) {
                    int row = i >> 6, u = i & 63;
                    cp16(sb + (unsigned)(ACT_OFF + row * 1040 + u * 16),
                         gx + row * 512 + u * 8);
                }
                cp_commit();
            }
        }
    }

    // c_n
    if (tid < 256)
        out[(size_t)SEQL * BATCH * HID + (size_t)BATCH * HID
            + (size_t)ub * HID + hc0 + uhcl] = cst;
}

extern "C" void kernel_launch(void* const* d_in, const int* in_sizes, int n_in,
                              void* d_out, int out_size)
{
    const float* input = (const float*)d_in[0];
    const float* Wih   = (const float*)d_in[1];
    const float* Whh   = (const float*)d_in[2];
    const float* bih   = (const float*)d_in[3];
    const float* bhh   = (const float*)d_in[4];
    float* out = (float*)d_out;

    static int configured = 0;
    if (!configured) {
        cudaFuncSetAttribute(lstm_persistent,
                             cudaFuncAttributeMaxDynamicSharedMemorySize, SMEM_TOTAL);
        configured = 1;
    }

    xconv<<<SEQL, 256>>>(input);
    lstm_persistent<<<NCTA, NTHR, SMEM_TOTAL>>>(Wih, Whh, bih, bhh, out);
}